// round 10
// baseline (speedup 1.0000x reference)
#include <cuda_runtime.h>
#include <cuda_bf16.h>
#include <cstdint>

#define N_TOK 32768
#define DIM   256
#define NCODE 1024
#define TAU   3.0f
#define TAU2  0.75f
#define CAP   48

// d_out layout (float32): z_q_st, loss, indices, new_cluster_size,
// new_embedding_avg, new_embedding
#define OFF_ZQ   0
#define OFF_LOSS (N_TOK * DIM)
#define OFF_IDX  (OFF_LOSS + 1)
#define OFF_CS   (OFF_IDX + N_TOK)
#define OFF_AVG  (OFF_CS + NCODE)
#define OFF_EMB  (OFF_AVG + NCODE * DIM)

#define TILE_B   10240                   // 128 rows x 80 B (64 B data + pad)

__device__ __align__(16) float g_enorm[NCODE];
__device__ float g_counts[NCODE];
__device__ __align__(16) float g_esum[NCODE * DIM];
__device__ float g_loss;
__device__ float g_nsum;
// tile-contiguous bf16 images: gAt[block][kc][row*80 + c*2], gBt[n][kc][...]
__device__ __align__(16) uint8_t gAt[(N_TOK / 128) * 8 * TILE_B];   // 21 MB
__device__ __align__(16) uint8_t gBt[(NCODE / 128) * 8 * TILE_B];   // 655 KB
__device__ __align__(16) int g_cnt[N_TOK];
__device__ unsigned g_minu[N_TOK];
__device__ unsigned long long g_cand64[N_TOK * CAP];   // (mapped dist, code)

// ---------------------------------------------------------------------------
__device__ __forceinline__ uint32_t smem_u32(const void* p) {
    uint32_t a;
    asm("{ .reg .u64 t; cvta.to.shared.u64 t, %1; cvt.u32.u64 %0, t; }"
        : "=r"(a) : "l"(p));
    return a;
}
#define MBAR_INIT(a, c) asm volatile("mbarrier.init.shared.b64 [%0], %1;" \
    :: "r"(a), "r"(c) : "memory")
#define MBAR_EXPECT_TX(a, b) asm volatile(                                    \
    "mbarrier.arrive.expect_tx.shared.b64 _, [%0], %1;"                       \
    :: "r"(a), "r"(b) : "memory")
#define MBAR_WAIT(a, ph) do {                                               \
    uint32_t _m = (a), _p = (ph), _d;                                       \
    asm volatile("{\n\t.reg .pred p;\n\t"                                   \
        "mbarrier.try_wait.parity.acquire.cta.shared::cta.b64 p, [%1], %2;\n\t" \
        "selp.b32 %0, 1, 0, p;\n\t}" : "=r"(_d) : "r"(_m), "r"(_p) : "memory"); \
    if (!_d) {                                                              \
        asm volatile("{\n\t.reg .pred P1;\n\tWL%=:\n\t"                     \
            "mbarrier.try_wait.parity.acquire.cta.shared::cta.b64 P1, [%0], %1, 0x989680;\n\t" \
            "@P1 bra.uni WD%=;\n\tbra.uni WL%=;\n\tWD%=:\n\t}"              \
            :: "r"(_m), "r"(_p) : "memory");                                \
    } } while (0)
#define FENCE_ASYNC() asm volatile("fence.proxy.async.shared::cta;" ::: "memory")

__device__ __forceinline__ void bulk_g2s(uint32_t dst, const void* src,
                                         uint32_t bytes, uint32_t mbar) {
    asm volatile(
        "cp.async.bulk.shared::cta.global.mbarrier::complete_tx::bytes "
        "[%0], [%1], %2, [%3];"
        :: "r"(dst), "l"(__cvta_generic_to_global(src)), "r"(bytes), "r"(mbar)
        : "memory");
}
__device__ __forceinline__ void red_add_v4(float* gptr, float4 v) {
    asm volatile("red.global.add.v4.f32 [%0], {%1, %2, %3, %4};"
                 :: "l"(__cvta_generic_to_global(gptr)),
                    "f"(v.x), "f"(v.y), "f"(v.z), "f"(v.w) : "memory");
}

#define LDSM4(r0, r1, r2, r3, addr) asm volatile(                              \
    "ldmatrix.sync.aligned.m8n8.x4.shared.b16 {%0,%1,%2,%3}, [%4];"            \
    : "=r"(r0), "=r"(r1), "=r"(r2), "=r"(r3) : "r"(addr))

#define MMA(c, a0, a1, a2, a3, b0, b1) asm volatile(                           \
    "mma.sync.aligned.m16n8k16.row.col.f32.bf16.bf16.f32 "                     \
    "{%0,%1,%2,%3},{%4,%5,%6,%7},{%8,%9},{%0,%1,%2,%3};"                       \
    : "+f"((c)[0]), "+f"((c)[1]), "+f"((c)[2]), "+f"((c)[3])                   \
    : "r"(a0), "r"(a1), "r"(a2), "r"(a3), "r"(b0), "r"(b1))

__device__ __forceinline__ unsigned mapf(float d) {
    unsigned u = __float_as_uint(d);
    return (u & 0x80000000u) ? ~u : (u | 0x80000000u);
}
__device__ __forceinline__ float unmapf(unsigned x) {
    return (x & 0x80000000u) ? __uint_as_float(x & 0x7fffffffu)
                             : __uint_as_float(~x);
}

// ---------------------------------------------------------------------------
__global__ void enorm_kernel(const float* __restrict__ emb) {
    int w = (blockIdx.x * blockDim.x + threadIdx.x) >> 5;
    int lane = threadIdx.x & 31;
    if (w >= NCODE) return;
    const float4* p = (const float4*)(emb + (size_t)w * DIM);
    float s = 0.0f;
#pragma unroll
    for (int c = 0; c < 2; c++) {
        float4 v = p[lane + 32 * c];
        s += v.x * v.x + v.y * v.y + v.z * v.z + v.w * v.w;
    }
#pragma unroll
    for (int o = 16; o >= 1; o >>= 1) s += __shfl_xor_sync(0xffffffffu, s, o);
    if (lane == 0) g_enorm[w] = s;
}

// prep: fp32 -> bf16 into tile-contiguous layout; also zeroes scratch.
#define AC (N_TOK * DIM / 8)             // 1,048,576
#define BC (NCODE * DIM / 8)             // 32,768
#define ZC (NCODE * DIM / 4)             // 65,536
__global__ void prep_kernel(const float* __restrict__ z, const float* __restrict__ emb) {
    int p = blockIdx.x * blockDim.x + threadIdx.x;
    if (p < AC) {
        int t = p >> 9, w = p & 511;             // tile, chunk-within
        int row = w >> 2, c4 = w & 3;
        int b = t >> 3, kc = t & 7;
        const float* src = z + (size_t)(b * 128 + row) * DIM + kc * 32 + c4 * 8;
        float4 v0 = *(const float4*)src;
        float4 v1 = *(const float4*)(src + 4);
        __nv_bfloat162 o0 = __halves2bfloat162(__float2bfloat16_rn(v0.x), __float2bfloat16_rn(v0.y));
        __nv_bfloat162 o1 = __halves2bfloat162(__float2bfloat16_rn(v0.z), __float2bfloat16_rn(v0.w));
        __nv_bfloat162 o2 = __halves2bfloat162(__float2bfloat16_rn(v1.x), __float2bfloat16_rn(v1.y));
        __nv_bfloat162 o3 = __halves2bfloat162(__float2bfloat16_rn(v1.z), __float2bfloat16_rn(v1.w));
        uint4 pack = {*(uint32_t*)&o0, *(uint32_t*)&o1, *(uint32_t*)&o2, *(uint32_t*)&o3};
        *(uint4*)(gAt + (size_t)t * TILE_B + row * 80 + c4 * 16) = pack;
    } else if (p < AC + BC) {
        int q = p - AC;
        int t = q >> 9, w = q & 511;
        int row = w >> 2, c4 = w & 3;
        int n = t >> 3, kc = t & 7;
        const float* src = emb + (size_t)(n * 128 + row) * DIM + kc * 32 + c4 * 8;
        float4 v0 = *(const float4*)src;
        float4 v1 = *(const float4*)(src + 4);
        __nv_bfloat162 o0 = __halves2bfloat162(__float2bfloat16_rn(v0.x), __float2bfloat16_rn(v0.y));
        __nv_bfloat162 o1 = __halves2bfloat162(__float2bfloat16_rn(v0.z), __float2bfloat16_rn(v0.w));
        __nv_bfloat162 o2 = __halves2bfloat162(__float2bfloat16_rn(v1.x), __float2bfloat16_rn(v1.y));
        __nv_bfloat162 o3 = __halves2bfloat162(__float2bfloat16_rn(v1.z), __float2bfloat16_rn(v1.w));
        uint4 pack = {*(uint32_t*)&o0, *(uint32_t*)&o1, *(uint32_t*)&o2, *(uint32_t*)&o3};
        *(uint4*)(gBt + (size_t)t * TILE_B + row * 80 + c4 * 16) = pack;
    } else {
        int zi = p - AC - BC;
        if (zi >= ZC) return;
        ((float4*)g_esum)[zi] = make_float4(0.f, 0.f, 0.f, 0.f);
        if (zi < N_TOK / 4) ((int4*)g_cnt)[zi] = make_int4(0, 0, 0, 0);
        if (zi < NCODE / 4) ((float4*)g_counts)[zi] = make_float4(0.f, 0.f, 0.f, 0.f);
        if (zi == 0) g_loss = 0.0f;
    }
}

// ---------------------------------------------------------------------------
// Main: bulk-copy-fed bf16 HMMA approx GEMM + windowed candidate collection
// (candidates packed (mapped_dist, code) -> global).
// ---------------------------------------------------------------------------
#define STAGE_SZ 20480                   // A 10240 + B 10240
#define SM_EN    81920                   // 4 KB
#define SM_MINU  86016                   // 128 x u32
#define SM_MBAR  86528                   // 4 x 8 B
#define SM_TOTAL 86592

__global__ __launch_bounds__(256, 2)
void vq_main_kernel() {
    extern __shared__ char smem[];
    const uint32_t sb = smem_u32(smem);
    const int tid  = threadIdx.x;
    const int lane = tid & 31;
    const int wid  = tid >> 5;
    const int wm   = wid >> 2;           // 0..1  (M half)
    const int wn   = wid & 3;            // 0..3  (N quarter, 32 cols)
    const int rowBase = blockIdx.x * 128;

    float*    sEnorm = (float*)(smem + SM_EN);
    unsigned* sMinU  = (unsigned*)(smem + SM_MINU);

#pragma unroll
    for (int i = 0; i < 4; i++) sEnorm[tid + i * 256] = g_enorm[tid + i * 256];
    if (tid < 128) sMinU[tid] = 0xffffffffu;
    if (tid == 0) {
#pragma unroll
        for (int s = 0; s < 4; s++) MBAR_INIT(sb + SM_MBAR + s * 8, 1);
    }
    __syncthreads();
    FENCE_ASYNC();

    // producer: j = n*8 + kc
#define ISSUE(j) do {                                                          \
    int _s = (j) & 3;                                                          \
    uint32_t _st = sb + _s * STAGE_SZ;                                         \
    uint32_t _mb = sb + SM_MBAR + _s * 8;                                      \
    MBAR_EXPECT_TX(_mb, STAGE_SZ);                                             \
    bulk_g2s(_st, gAt + (size_t)(blockIdx.x * 8 + ((j) & 7)) * TILE_B,         \
             TILE_B, _mb);                                                     \
    bulk_g2s(_st + TILE_B, gBt + (size_t)(j) * TILE_B, TILE_B, _mb);           \
} while (0)

    if (tid == 0) { ISSUE(0); ISSUE(1); ISSUE(2); }

    // ldmatrix per-lane address offsets (bytes), row stride 80B
    const uint32_t aOff = (uint32_t)((wm * 64 + (lane & 15)) * 80 + (lane >> 4) * 16);
    const uint32_t bOff = (uint32_t)((wn * 32 + (lane & 7) + ((lane >> 4) << 3)) * 80
                                     + ((lane >> 3) & 1) * 16);

    float acc[4][4][4];
#pragma unroll
    for (int m = 0; m < 4; m++)
#pragma unroll
        for (int nf = 0; nf < 4; nf++)
#pragma unroll
            for (int v = 0; v < 4; v++) acc[m][nf][v] = 0.0f;

#define EMIT(dd, cc, rglob) do {                                               \
    int _p = atomicAdd(&g_cnt[rglob], 1);                                      \
    if (_p < CAP)                                                              \
        g_cand64[(size_t)(rglob) * CAP + _p] =                                 \
            ((unsigned long long)mapf(dd) << 32) | (unsigned)(cc);             \
} while (0)

    for (int it = 0; it < 64; it++) {
        MBAR_WAIT(sb + SM_MBAR + (it & 3) * 8, (it >> 2) & 1);

        const uint32_t stBase = sb + (it & 3) * STAGE_SZ;
        const uint32_t aB = stBase + aOff;
        const uint32_t bB = stBase + TILE_B + bOff;

#pragma unroll
        for (int s = 0; s < 2; s++) {                    // two k16 steps
            uint32_t b[4][2];
#pragma unroll
            for (int q = 0; q < 2; q++) {
                uint32_t r0, r1, r2, r3;
                LDSM4(r0, r1, r2, r3, bB + q * 1280 + s * 32);
                b[2 * q][0] = r0; b[2 * q][1] = r1;
                b[2 * q + 1][0] = r2; b[2 * q + 1][1] = r3;
            }
#pragma unroll
            for (int m = 0; m < 4; m++) {
                uint32_t a0, a1, a2, a3;
                LDSM4(a0, a1, a2, a3, aB + m * 1280 + s * 32);
#pragma unroll
                for (int nf = 0; nf < 4; nf++)
                    MMA(acc[m][nf], a0, a1, a2, a3, b[nf][0], b[nf][1]);
            }
        }

        if ((it & 7) == 7) {                             // end of n-tile
            const int n = it >> 3;
            const int colB = n * 128 + wn * 32 + 2 * (lane & 3);
            // pass 1: settle per-row approx min
#pragma unroll
            for (int m = 0; m < 4; m++) {
                int r0 = wm * 64 + m * 16 + (lane >> 2);
                float bd0 = 3.4e38f, bd1 = 3.4e38f;
#pragma unroll
                for (int nf = 0; nf < 4; nf++) {
                    float2 en = *(const float2*)&sEnorm[colB + nf * 8];
                    bd0 = fminf(bd0, fminf(en.x - 2.0f * acc[m][nf][0],
                                           en.y - 2.0f * acc[m][nf][1]));
                    bd1 = fminf(bd1, fminf(en.x - 2.0f * acc[m][nf][2],
                                           en.y - 2.0f * acc[m][nf][3]));
                }
#pragma unroll
                for (int off = 1; off <= 2; off <<= 1) {
                    bd0 = fminf(bd0, __shfl_xor_sync(0xffffffffu, bd0, off));
                    bd1 = fminf(bd1, __shfl_xor_sync(0xffffffffu, bd1, off));
                }
                if ((lane & 3) == 0) {
                    atomicMin(&sMinU[r0], mapf(bd0));
                    atomicMin(&sMinU[r0 + 8], mapf(bd1));
                }
            }
            __syncthreads();
            // pass 2: emit candidates within TAU of settled min (to global)
#pragma unroll
            for (int m = 0; m < 4; m++) {
                int r0 = wm * 64 + m * 16 + (lane >> 2);
                float thr0 = unmapf(sMinU[r0]) + TAU;
                float thr1 = unmapf(sMinU[r0 + 8]) + TAU;
#pragma unroll
                for (int nf = 0; nf < 4; nf++) {
                    float2 en = *(const float2*)&sEnorm[colB + nf * 8];
                    float d0 = en.x - 2.0f * acc[m][nf][0];
                    float d1 = en.y - 2.0f * acc[m][nf][1];
                    float d2 = en.x - 2.0f * acc[m][nf][2];
                    float d3 = en.y - 2.0f * acc[m][nf][3];
                    int c0 = colB + nf * 8;
                    if (d0 < thr0) EMIT(d0, c0,     rowBase + r0);
                    if (d1 < thr0) EMIT(d1, c0 + 1, rowBase + r0);
                    if (d2 < thr1) EMIT(d2, c0,     rowBase + r0 + 8);
                    if (d3 < thr1) EMIT(d3, c0 + 1, rowBase + r0 + 8);
                    acc[m][nf][0] = 0.0f; acc[m][nf][1] = 0.0f;
                    acc[m][nf][2] = 0.0f; acc[m][nf][3] = 0.0f;
                }
            }
        }
        __syncthreads();                                 // stage consumed
        if (tid == 0 && it + 3 < 64) ISSUE(it + 3);
    }

    // dump final per-row approx min
    if (tid < 128) g_minu[rowBase + tid] = sMinU[tid];
}

// ---------------------------------------------------------------------------
// Refine + output kernel: grid N_TOK/16, 256 threads.
// Phase A: lane-per-candidate exact fp32 refinement of candidates within
//          TAU2 of the settled approx min; packed-u64 warp argmin.
// Phase B: vectorized float4 z_q_st / loss / esum.
// ---------------------------------------------------------------------------
__global__ __launch_bounds__(256, 8)
void outref_kernel(const float* __restrict__ z, const float* __restrict__ emb,
                   float* __restrict__ out) {
    __shared__ __align__(16) float sZ[8][256];
    __shared__ int   sBestC[16];
    __shared__ float sRed[8];
    const int tid  = threadIdx.x;
    const int lane = tid & 31;
    const int wid  = tid >> 5;
    const int rowBase = blockIdx.x * 16;

#pragma unroll
    for (int rr = 0; rr < 2; rr++) {
        int r = rowBase + wid * 2 + rr;
        int cnt = g_cnt[r]; if (cnt > CAP) cnt = CAP;
        unsigned mthr = mapf(unmapf(g_minu[r]) + TAU2);
        float4* sZ4 = (float4*)&sZ[wid][0];
        const float4* zr4 = (const float4*)(z + (size_t)r * DIM);
        sZ4[lane]      = zr4[lane];
        sZ4[lane + 32] = zr4[lane + 32];
        __syncwarp();

        unsigned long long best = ~0ull;
        for (int base = 0; base < cnt; base += 32) {
            int ci = base + lane;
            if (ci < cnt) {
                unsigned long long pk = g_cand64[(size_t)r * CAP + ci];
                unsigned md = (unsigned)(pk >> 32);
                int c = (int)(unsigned)(pk & 0xffffffffull);
                if (md <= mthr) {
                    const float4* er = (const float4*)(emb + (size_t)c * DIM);
                    float s0 = 0.f, s1 = 0.f, s2 = 0.f, s3 = 0.f;
#pragma unroll
                    for (int j = 0; j < 64; j += 4) {
                        float4 e0 = er[j], e1 = er[j + 1], e2 = er[j + 2], e3 = er[j + 3];
                        float4 z0 = sZ4[j], z1 = sZ4[j + 1], z2 = sZ4[j + 2], z3 = sZ4[j + 3];
                        s0 += e0.x * z0.x + e0.y * z0.y + e0.z * z0.z + e0.w * z0.w;
                        s1 += e1.x * z1.x + e1.y * z1.y + e1.z * z1.z + e1.w * z1.w;
                        s2 += e2.x * z2.x + e2.y * z2.y + e2.z * z2.z + e2.w * z2.w;
                        s3 += e3.x * z3.x + e3.y * z3.y + e3.z * z3.z + e3.w * z3.w;
                    }
                    float dot = (s0 + s1) + (s2 + s3);
                    float dd = g_enorm[c] - 2.0f * dot;
                    unsigned long long cand =
                        ((unsigned long long)mapf(dd) << 32) | (unsigned)c;
                    if (cand < best) best = cand;
                }
            }
        }
#pragma unroll
        for (int off = 16; off >= 1; off >>= 1) {
            unsigned long long o = __shfl_xor_sync(0xffffffffu, best, off);
            if (o < best) best = o;
        }
        if (lane == 0) {
            int bc = (int)(unsigned)(best & 0xffffffffull);
            sBestC[wid * 2 + rr] = bc;
            out[OFF_IDX + r] = (float)bc;
            atomicAdd(&g_counts[bc], 1.0f);
        }
    }
    __syncthreads();

    // phase B: 4 row-groups x 64 column-threads, float4 everywhere
    float lossAcc = 0.0f;
    const int c4 = (tid & 63) * 4;
    const int rg = tid >> 6;
#pragma unroll
    for (int k = 0; k < 4; k++) {
        int rr   = rg * 4 + k;
        int code = sBestC[rr];
        int row  = rowBase + rr;
        float4 e  = *(const float4*)(emb + (size_t)code * DIM + c4);
        float4 zv = *(const float4*)(z + (size_t)row * DIM + c4);
        float4 df = make_float4(e.x - zv.x, e.y - zv.y, e.z - zv.z, e.w - zv.w);
        float4 q  = make_float4(zv.x + df.x, zv.y + df.y, zv.z + df.z, zv.w + df.w);
        *(float4*)(out + OFF_ZQ + (size_t)row * DIM + c4) = q;
        lossAcc += df.x * df.x + df.y * df.y + df.z * df.z + df.w * df.w;
        red_add_v4(&g_esum[code * DIM + c4], zv);
    }
#pragma unroll
    for (int o = 16; o >= 1; o >>= 1) lossAcc += __shfl_xor_sync(0xffffffffu, lossAcc, o);
    if (lane == 0) sRed[wid] = lossAcc;
    __syncthreads();
    if (tid < 8) {
        float v = sRed[tid];
#pragma unroll
        for (int o = 4; o >= 1; o >>= 1) v += __shfl_xor_sync(0xffu, v, o, 8);
        if (tid == 0) atomicAdd(&g_loss, v);
    }
}

// ---------------------------------------------------------------------------
__global__ void fin1_kernel(const float* __restrict__ cs, float* __restrict__ out) {
    int k = threadIdx.x;
    float ncs = cs[k] * 0.99f + 0.01f * g_counts[k];
    out[OFF_CS + k] = ncs;
    __shared__ float red[32];
    float v = ncs;
#pragma unroll
    for (int o = 16; o >= 1; o >>= 1) v += __shfl_xor_sync(0xffffffffu, v, o);
    if ((k & 31) == 0) red[k >> 5] = v;
    __syncthreads();
    if (k < 32) {
        float t = red[k];
#pragma unroll
        for (int o = 16; o >= 1; o >>= 1) t += __shfl_xor_sync(0xffffffffu, t, o);
        if (k == 0) {
            g_nsum = t;
            out[OFF_LOSS] = 0.25f * g_loss / (float)(N_TOK * DIM);
        }
    }
}

__global__ void fin2_kernel(const float* __restrict__ avg, float* __restrict__ out) {
    int i = blockIdx.x * blockDim.x + threadIdx.x;
    float navg = avg[i] * 0.99f + 0.01f * g_esum[i];
    out[OFF_AVG + i] = navg;
    int k = i >> 8;
    float ncs = out[OFF_CS + k];
    float csn = (ncs + 1e-6f) / (g_nsum + (float)NCODE * 1e-6f);
    out[OFF_EMB + i] = navg / csn;
}

// ---------------------------------------------------------------------------
extern "C" void kernel_launch(void* const* d_in, const int* in_sizes, int n_in,
                              void* d_out, int out_size) {
    const float* z   = (const float*)d_in[0];
    const float* emb = (const float*)d_in[1];
    const float* cs  = (const float*)d_in[2];
    const float* avg = (const float*)d_in[3];
    float* out = (float*)d_out;

    cudaFuncSetAttribute(vq_main_kernel,
                         cudaFuncAttributeMaxDynamicSharedMemorySize, SM_TOTAL);

    enorm_kernel<<<(NCODE * 32) / 256, 256>>>(emb);
    prep_kernel<<<(AC + BC + ZC + 255) / 256, 256>>>(z, emb);
    vq_main_kernel<<<N_TOK / 128, 256, SM_TOTAL>>>();
    outref_kernel<<<N_TOK / 16, 256>>>(z, emb, out);
    fin1_kernel<<<1, 1024>>>(cs, out);
    fin2_kernel<<<(NCODE * DIM) / 256, 256>>>(avg, out);
}

// round 11
// speedup vs baseline: 1.6381x; 1.6381x over previous
#include <cuda_runtime.h>
#include <cuda_bf16.h>
#include <cstdint>

#define N_TOK 32768
#define DIM   256
#define NCODE 1024
#define TAU   3.0f
#define TAU2  0.75f
#define CAP   48

// d_out layout (float32): z_q_st, loss, indices, new_cluster_size,
// new_embedding_avg, new_embedding
#define OFF_ZQ   0
#define OFF_LOSS (N_TOK * DIM)
#define OFF_IDX  (OFF_LOSS + 1)
#define OFF_CS   (OFF_IDX + N_TOK)
#define OFF_AVG  (OFF_CS + NCODE)
#define OFF_EMB  (OFF_AVG + NCODE * DIM)

#define TILE_B   10240                   // 128 rows x 80 B (64 B data + pad)

__device__ __align__(16) float g_enorm[NCODE];
__device__ float g_counts[NCODE];
__device__ __align__(16) float g_esum[NCODE * DIM];
__device__ float g_loss;
__device__ float g_nsum;
// tile-contiguous bf16 images: gAt[block][kc][row*80 + c*2], gBt[n][kc][...]
__device__ __align__(16) uint8_t gAt[(N_TOK / 128) * 8 * TILE_B];   // 21 MB
__device__ __align__(16) uint8_t gBt[(NCODE / 128) * 8 * TILE_B];   // 655 KB
__device__ int g_cnt[N_TOK];
__device__ unsigned g_minu[N_TOK];
__device__ unsigned long long g_cand64[N_TOK * CAP];   // (mapped dist, code)

// ---------------------------------------------------------------------------
__device__ __forceinline__ uint32_t smem_u32(const void* p) {
    uint32_t a;
    asm("{ .reg .u64 t; cvta.to.shared.u64 t, %1; cvt.u32.u64 %0, t; }"
        : "=r"(a) : "l"(p));
    return a;
}
#define MBAR_INIT(a, c) asm volatile("mbarrier.init.shared.b64 [%0], %1;" \
    :: "r"(a), "r"(c) : "memory")
#define MBAR_EXPECT_TX(a, b) asm volatile(                                    \
    "mbarrier.arrive.expect_tx.shared.b64 _, [%0], %1;"                       \
    :: "r"(a), "r"(b) : "memory")
#define MBAR_WAIT(a, ph) do {                                               \
    uint32_t _m = (a), _p = (ph), _d;                                       \
    asm volatile("{\n\t.reg .pred p;\n\t"                                   \
        "mbarrier.try_wait.parity.acquire.cta.shared::cta.b64 p, [%1], %2;\n\t" \
        "selp.b32 %0, 1, 0, p;\n\t}" : "=r"(_d) : "r"(_m), "r"(_p) : "memory"); \
    if (!_d) {                                                              \
        asm volatile("{\n\t.reg .pred P1;\n\tWL%=:\n\t"                     \
            "mbarrier.try_wait.parity.acquire.cta.shared::cta.b64 P1, [%0], %1, 0x989680;\n\t" \
            "@P1 bra.uni WD%=;\n\tbra.uni WL%=;\n\tWD%=:\n\t}"              \
            :: "r"(_m), "r"(_p) : "memory");                                \
    } } while (0)
#define FENCE_ASYNC() asm volatile("fence.proxy.async.shared::cta;" ::: "memory")

__device__ __forceinline__ void bulk_g2s(uint32_t dst, const void* src,
                                         uint32_t bytes, uint32_t mbar) {
    asm volatile(
        "cp.async.bulk.shared::cta.global.mbarrier::complete_tx::bytes "
        "[%0], [%1], %2, [%3];"
        :: "r"(dst), "l"(__cvta_generic_to_global(src)), "r"(bytes), "r"(mbar)
        : "memory");
}
__device__ __forceinline__ void red_add_v4(float* gptr, float4 v) {
    asm volatile("red.global.add.v4.f32 [%0], {%1, %2, %3, %4};"
                 :: "l"(__cvta_generic_to_global(gptr)),
                    "f"(v.x), "f"(v.y), "f"(v.z), "f"(v.w) : "memory");
}

#define LDSM4(r0, r1, r2, r3, addr) asm volatile(                              \
    "ldmatrix.sync.aligned.m8n8.x4.shared.b16 {%0,%1,%2,%3}, [%4];"            \
    : "=r"(r0), "=r"(r1), "=r"(r2), "=r"(r3) : "r"(addr))

#define MMA(c, a0, a1, a2, a3, b0, b1) asm volatile(                           \
    "mma.sync.aligned.m16n8k16.row.col.f32.bf16.bf16.f32 "                     \
    "{%0,%1,%2,%3},{%4,%5,%6,%7},{%8,%9},{%0,%1,%2,%3};"                       \
    : "+f"((c)[0]), "+f"((c)[1]), "+f"((c)[2]), "+f"((c)[3])                   \
    : "r"(a0), "r"(a1), "r"(a2), "r"(a3), "r"(b0), "r"(b1))

__device__ __forceinline__ unsigned mapf(float d) {
    unsigned u = __float_as_uint(d);
    return (u & 0x80000000u) ? ~u : (u | 0x80000000u);
}
__device__ __forceinline__ float unmapf(unsigned x) {
    return (x & 0x80000000u) ? __uint_as_float(x & 0x7fffffffu)
                             : __uint_as_float(~x);
}

// ---------------------------------------------------------------------------
__global__ void enorm_kernel(const float* __restrict__ emb) {
    int w = (blockIdx.x * blockDim.x + threadIdx.x) >> 5;
    int lane = threadIdx.x & 31;
    if (w >= NCODE) return;
    const float4* p = (const float4*)(emb + (size_t)w * DIM);
    float s = 0.0f;
#pragma unroll
    for (int c = 0; c < 2; c++) {
        float4 v = p[lane + 32 * c];
        s += v.x * v.x + v.y * v.y + v.z * v.z + v.w * v.w;
    }
#pragma unroll
    for (int o = 16; o >= 1; o >>= 1) s += __shfl_xor_sync(0xffffffffu, s, o);
    if (lane == 0) g_enorm[w] = s;
}

// prep: fp32 -> bf16 into tile-contiguous layout; also zeroes scratch.
#define AC (N_TOK * DIM / 8)             // 1,048,576
#define BC (NCODE * DIM / 8)             // 32,768
#define ZC (NCODE * DIM / 4)             // 65,536
__global__ void prep_kernel(const float* __restrict__ z, const float* __restrict__ emb) {
    int p = blockIdx.x * blockDim.x + threadIdx.x;
    if (p < AC) {
        int t = p >> 9, w = p & 511;             // tile, chunk-within
        int row = w >> 2, c4 = w & 3;
        int b = t >> 3, kc = t & 7;
        const float* src = z + (size_t)(b * 128 + row) * DIM + kc * 32 + c4 * 8;
        float4 v0 = *(const float4*)src;
        float4 v1 = *(const float4*)(src + 4);
        __nv_bfloat162 o0 = __halves2bfloat162(__float2bfloat16_rn(v0.x), __float2bfloat16_rn(v0.y));
        __nv_bfloat162 o1 = __halves2bfloat162(__float2bfloat16_rn(v0.z), __float2bfloat16_rn(v0.w));
        __nv_bfloat162 o2 = __halves2bfloat162(__float2bfloat16_rn(v1.x), __float2bfloat16_rn(v1.y));
        __nv_bfloat162 o3 = __halves2bfloat162(__float2bfloat16_rn(v1.z), __float2bfloat16_rn(v1.w));
        uint4 pack = {*(uint32_t*)&o0, *(uint32_t*)&o1, *(uint32_t*)&o2, *(uint32_t*)&o3};
        *(uint4*)(gAt + (size_t)t * TILE_B + row * 80 + c4 * 16) = pack;
    } else if (p < AC + BC) {
        int q = p - AC;
        int t = q >> 9, w = q & 511;
        int row = w >> 2, c4 = w & 3;
        int n = t >> 3, kc = t & 7;
        const float* src = emb + (size_t)(n * 128 + row) * DIM + kc * 32 + c4 * 8;
        float4 v0 = *(const float4*)src;
        float4 v1 = *(const float4*)(src + 4);
        __nv_bfloat162 o0 = __halves2bfloat162(__float2bfloat16_rn(v0.x), __float2bfloat16_rn(v0.y));
        __nv_bfloat162 o1 = __halves2bfloat162(__float2bfloat16_rn(v0.z), __float2bfloat16_rn(v0.w));
        __nv_bfloat162 o2 = __halves2bfloat162(__float2bfloat16_rn(v1.x), __float2bfloat16_rn(v1.y));
        __nv_bfloat162 o3 = __halves2bfloat162(__float2bfloat16_rn(v1.z), __float2bfloat16_rn(v1.w));
        uint4 pack = {*(uint32_t*)&o0, *(uint32_t*)&o1, *(uint32_t*)&o2, *(uint32_t*)&o3};
        *(uint4*)(gBt + (size_t)t * TILE_B + row * 80 + c4 * 16) = pack;
    } else {
        int zi = p - AC - BC;
        if (zi >= ZC) return;
        ((float4*)g_esum)[zi] = make_float4(0.f, 0.f, 0.f, 0.f);
        if (zi < NCODE / 4) ((float4*)g_counts)[zi] = make_float4(0.f, 0.f, 0.f, 0.f);
        if (zi == 0) g_loss = 0.0f;
    }
}

// ---------------------------------------------------------------------------
// Main: bulk-copy-fed bf16 HMMA approx GEMM + windowed candidate collection.
// Candidates (mapped_dist, code) appended via SMEM counters, stored straight
// to global; counts + per-row approx minima dumped once at the end.
// ---------------------------------------------------------------------------
#define STAGE_SZ 20480                   // A 10240 + B 10240
#define SM_EN    81920                   // 4 KB
#define SM_MINU  86016                   // 128 x u32
#define SM_CNT   86528                   // 128 x int
#define SM_MBAR  87040                   // 4 x 8 B
#define SM_TOTAL 87104

__global__ __launch_bounds__(256, 2)
void vq_main_kernel() {
    extern __shared__ char smem[];
    const uint32_t sb = smem_u32(smem);
    const int tid  = threadIdx.x;
    const int lane = tid & 31;
    const int wid  = tid >> 5;
    const int wm   = wid >> 2;           // 0..1  (M half)
    const int wn   = wid & 3;            // 0..3  (N quarter, 32 cols)
    const int rowBase = blockIdx.x * 128;

    float*    sEnorm = (float*)(smem + SM_EN);
    unsigned* sMinU  = (unsigned*)(smem + SM_MINU);
    int*      sCnt   = (int*)(smem + SM_CNT);

#pragma unroll
    for (int i = 0; i < 4; i++) sEnorm[tid + i * 256] = g_enorm[tid + i * 256];
    if (tid < 128) { sMinU[tid] = 0xffffffffu; sCnt[tid] = 0; }
    if (tid == 0) {
#pragma unroll
        for (int s = 0; s < 4; s++) MBAR_INIT(sb + SM_MBAR + s * 8, 1);
    }
    __syncthreads();
    FENCE_ASYNC();

    // producer: j = n*8 + kc
#define ISSUE(j) do {                                                          \
    int _s = (j) & 3;                                                          \
    uint32_t _st = sb + _s * STAGE_SZ;                                         \
    uint32_t _mb = sb + SM_MBAR + _s * 8;                                      \
    MBAR_EXPECT_TX(_mb, STAGE_SZ);                                             \
    bulk_g2s(_st, gAt + (size_t)(blockIdx.x * 8 + ((j) & 7)) * TILE_B,         \
             TILE_B, _mb);                                                     \
    bulk_g2s(_st + TILE_B, gBt + (size_t)(j) * TILE_B, TILE_B, _mb);           \
} while (0)

    if (tid == 0) { ISSUE(0); ISSUE(1); ISSUE(2); }

    // ldmatrix per-lane address offsets (bytes), row stride 80B
    const uint32_t aOff = (uint32_t)((wm * 64 + (lane & 15)) * 80 + (lane >> 4) * 16);
    const uint32_t bOff = (uint32_t)((wn * 32 + (lane & 7) + ((lane >> 4) << 3)) * 80
                                     + ((lane >> 3) & 1) * 16);

    float acc[4][4][4];
#pragma unroll
    for (int m = 0; m < 4; m++)
#pragma unroll
        for (int nf = 0; nf < 4; nf++)
#pragma unroll
            for (int v = 0; v < 4; v++) acc[m][nf][v] = 0.0f;

    // smem counter, direct global store of packed (dist, code)
#define EMIT(dd, cc, rloc) do {                                                \
    int _p = atomicAdd(&sCnt[rloc], 1);                                        \
    if (_p < CAP)                                                              \
        g_cand64[(size_t)(rowBase + (rloc)) * CAP + _p] =                      \
            ((unsigned long long)mapf(dd) << 32) | (unsigned)(cc);             \
} while (0)

    for (int it = 0; it < 64; it++) {
        MBAR_WAIT(sb + SM_MBAR + (it & 3) * 8, (it >> 2) & 1);

        const uint32_t stBase = sb + (it & 3) * STAGE_SZ;
        const uint32_t aB = stBase + aOff;
        const uint32_t bB = stBase + TILE_B + bOff;

#pragma unroll
        for (int s = 0; s < 2; s++) {                    // two k16 steps
            uint32_t b[4][2];
#pragma unroll
            for (int q = 0; q < 2; q++) {
                uint32_t r0, r1, r2, r3;
                LDSM4(r0, r1, r2, r3, bB + q * 1280 + s * 32);
                b[2 * q][0] = r0; b[2 * q][1] = r1;
                b[2 * q + 1][0] = r2; b[2 * q + 1][1] = r3;
            }
#pragma unroll
            for (int m = 0; m < 4; m++) {
                uint32_t a0, a1, a2, a3;
                LDSM4(a0, a1, a2, a3, aB + m * 1280 + s * 32);
#pragma unroll
                for (int nf = 0; nf < 4; nf++)
                    MMA(acc[m][nf], a0, a1, a2, a3, b[nf][0], b[nf][1]);
            }
        }

        if ((it & 7) == 7) {                             // end of n-tile
            const int n = it >> 3;
            const int colB = n * 128 + wn * 32 + 2 * (lane & 3);
            // pass 1: settle per-row approx min
#pragma unroll
            for (int m = 0; m < 4; m++) {
                int r0 = wm * 64 + m * 16 + (lane >> 2);
                float bd0 = 3.4e38f, bd1 = 3.4e38f;
#pragma unroll
                for (int nf = 0; nf < 4; nf++) {
                    float2 en = *(const float2*)&sEnorm[colB + nf * 8];
                    bd0 = fminf(bd0, fminf(en.x - 2.0f * acc[m][nf][0],
                                           en.y - 2.0f * acc[m][nf][1]));
                    bd1 = fminf(bd1, fminf(en.x - 2.0f * acc[m][nf][2],
                                           en.y - 2.0f * acc[m][nf][3]));
                }
#pragma unroll
                for (int off = 1; off <= 2; off <<= 1) {
                    bd0 = fminf(bd0, __shfl_xor_sync(0xffffffffu, bd0, off));
                    bd1 = fminf(bd1, __shfl_xor_sync(0xffffffffu, bd1, off));
                }
                if ((lane & 3) == 0) {
                    atomicMin(&sMinU[r0], mapf(bd0));
                    atomicMin(&sMinU[r0 + 8], mapf(bd1));
                }
            }
            __syncthreads();
            // pass 2: emit candidates within TAU of settled min
#pragma unroll
            for (int m = 0; m < 4; m++) {
                int r0 = wm * 64 + m * 16 + (lane >> 2);
                float thr0 = unmapf(sMinU[r0]) + TAU;
                float thr1 = unmapf(sMinU[r0 + 8]) + TAU;
#pragma unroll
                for (int nf = 0; nf < 4; nf++) {
                    float2 en = *(const float2*)&sEnorm[colB + nf * 8];
                    float d0 = en.x - 2.0f * acc[m][nf][0];
                    float d1 = en.y - 2.0f * acc[m][nf][1];
                    float d2 = en.x - 2.0f * acc[m][nf][2];
                    float d3 = en.y - 2.0f * acc[m][nf][3];
                    int c0 = colB + nf * 8;
                    if (d0 < thr0) EMIT(d0, c0,     r0);
                    if (d1 < thr0) EMIT(d1, c0 + 1, r0);
                    if (d2 < thr1) EMIT(d2, c0,     r0 + 8);
                    if (d3 < thr1) EMIT(d3, c0 + 1, r0 + 8);
                    acc[m][nf][0] = 0.0f; acc[m][nf][1] = 0.0f;
                    acc[m][nf][2] = 0.0f; acc[m][nf][3] = 0.0f;
                }
            }
        }
        __syncthreads();                                 // stage consumed
        if (tid == 0 && it + 3 < 64) ISSUE(it + 3);
    }

    // dump counts (clamped) + final per-row approx min
    if (tid < 128) {
        int c = sCnt[tid];
        g_cnt[rowBase + tid]  = c > CAP ? CAP : c;
        g_minu[rowBase + tid] = sMinU[tid];
    }
}

// ---------------------------------------------------------------------------
// Refine + output kernel: grid N_TOK/16, 256 threads.
// Phase A: warp-cooperative exact fp32 refinement (coalesced emb reads),
//          TAU2 prefilter on stored approx dist before touching emb.
// Phase B: vectorized float4 z_q_st / loss / esum.
// ---------------------------------------------------------------------------
__global__ __launch_bounds__(256, 8)
void outref_kernel(const float* __restrict__ z, const float* __restrict__ emb,
                   float* __restrict__ out) {
    __shared__ int   sBestC[16];
    __shared__ float sRed[8];
    const int tid  = threadIdx.x;
    const int lane = tid & 31;
    const int wid  = tid >> 5;
    const int rowBase = blockIdx.x * 16;

#pragma unroll
    for (int rr = 0; rr < 2; rr++) {
        int r = rowBase + wid * 2 + rr;
        int cnt = g_cnt[r];
        unsigned mthr = mapf(unmapf(g_minu[r]) + TAU2);
        const float* zr = z + (size_t)r * DIM;
        float zv[8];
#pragma unroll
        for (int j = 0; j < 8; j++) zv[j] = zr[lane + 32 * j];
        float bestd = 3.4e38f; int bestc = 0x7fffffff;
        for (int i = 0; i < cnt; i++) {
            unsigned long long pk = g_cand64[(size_t)r * CAP + i];  // broadcast
            if ((unsigned)(pk >> 32) > mthr) continue;              // TAU2 filter
            int c = (int)(unsigned)(pk & 0xffffffffull);
            const float* er = emb + (size_t)c * DIM;
            float dot = 0.0f;
#pragma unroll
            for (int j = 0; j < 8; j++) dot += zv[j] * er[lane + 32 * j];
#pragma unroll
            for (int o = 16; o >= 1; o >>= 1) dot += __shfl_xor_sync(0xffffffffu, dot, o);
            float dd = g_enorm[c] - 2.0f * dot;
            if (dd < bestd || (dd == bestd && c < bestc)) { bestd = dd; bestc = c; }
        }
        if (lane == 0) {
            sBestC[wid * 2 + rr] = bestc;
            out[OFF_IDX + r] = (float)bestc;
            atomicAdd(&g_counts[bestc], 1.0f);
        }
    }
    __syncthreads();

    // phase B: 4 row-groups x 64 column-threads, float4 everywhere
    float lossAcc = 0.0f;
    const int c4 = (tid & 63) * 4;
    const int rg = tid >> 6;
#pragma unroll
    for (int k = 0; k < 4; k++) {
        int rr   = rg * 4 + k;
        int code = sBestC[rr];
        int row  = rowBase + rr;
        float4 e  = *(const float4*)(emb + (size_t)code * DIM + c4);
        float4 zv = *(const float4*)(z + (size_t)row * DIM + c4);
        float4 df = make_float4(e.x - zv.x, e.y - zv.y, e.z - zv.z, e.w - zv.w);
        float4 q  = make_float4(zv.x + df.x, zv.y + df.y, zv.z + df.z, zv.w + df.w);
        *(float4*)(out + OFF_ZQ + (size_t)row * DIM + c4) = q;
        lossAcc += df.x * df.x + df.y * df.y + df.z * df.z + df.w * df.w;
        red_add_v4(&g_esum[code * DIM + c4], zv);
    }
#pragma unroll
    for (int o = 16; o >= 1; o >>= 1) lossAcc += __shfl_xor_sync(0xffffffffu, lossAcc, o);
    if (lane == 0) sRed[wid] = lossAcc;
    __syncthreads();
    if (tid < 8) {
        float v = sRed[tid];
#pragma unroll
        for (int o = 4; o >= 1; o >>= 1) v += __shfl_xor_sync(0xffu, v, o, 8);
        if (tid == 0) atomicAdd(&g_loss, v);
    }
}

// ---------------------------------------------------------------------------
__global__ void fin1_kernel(const float* __restrict__ cs, float* __restrict__ out) {
    int k = threadIdx.x;
    float ncs = cs[k] * 0.99f + 0.01f * g_counts[k];
    out[OFF_CS + k] = ncs;
    __shared__ float red[32];
    float v = ncs;
#pragma unroll
    for (int o = 16; o >= 1; o >>= 1) v += __shfl_xor_sync(0xffffffffu, v, o);
    if ((k & 31) == 0) red[k >> 5] = v;
    __syncthreads();
    if (k < 32) {
        float t = red[k];
#pragma unroll
        for (int o = 16; o >= 1; o >>= 1) t += __shfl_xor_sync(0xffffffffu, t, o);
        if (k == 0) {
            g_nsum = t;
            out[OFF_LOSS] = 0.25f * g_loss / (float)(N_TOK * DIM);
        }
    }
}

__global__ void fin2_kernel(const float* __restrict__ avg, float* __restrict__ out) {
    int i = blockIdx.x * blockDim.x + threadIdx.x;
    float navg = avg[i] * 0.99f + 0.01f * g_esum[i];
    out[OFF_AVG + i] = navg;
    int k = i >> 8;
    float ncs = out[OFF_CS + k];
    float csn = (ncs + 1e-6f) / (g_nsum + (float)NCODE * 1e-6f);
    out[OFF_EMB + i] = navg / csn;
}

// ---------------------------------------------------------------------------
extern "C" void kernel_launch(void* const* d_in, const int* in_sizes, int n_in,
                              void* d_out, int out_size) {
    const float* z   = (const float*)d_in[0];
    const float* emb = (const float*)d_in[1];
    const float* cs  = (const float*)d_in[2];
    const float* avg = (const float*)d_in[3];
    float* out = (float*)d_out;

    cudaFuncSetAttribute(vq_main_kernel,
                         cudaFuncAttributeMaxDynamicSharedMemorySize, SM_TOTAL);

    enorm_kernel<<<(NCODE * 32) / 256, 256>>>(emb);
    prep_kernel<<<(AC + BC + ZC + 255) / 256, 256>>>(z, emb);
    vq_main_kernel<<<N_TOK / 128, 256, SM_TOTAL>>>();
    outref_kernel<<<N_TOK / 16, 256>>>(z, emb, out);
    fin1_kernel<<<1, 1024>>>(cs, out);
    fin2_kernel<<<(NCODE * DIM) / 256, 256>>>(avg, out);
}

// round 12
// speedup vs baseline: 1.6636x; 1.0156x over previous
#include <cuda_runtime.h>
#include <cuda_bf16.h>
#include <cstdint>

#define N_TOK 32768
#define DIM   256
#define NCODE 1024
#define TAU   3.0f
#define TAU2  0.75f
#define CAP   48

// d_out layout (float32): z_q_st, loss, indices, new_cluster_size,
// new_embedding_avg, new_embedding
#define OFF_ZQ   0
#define OFF_LOSS (N_TOK * DIM)
#define OFF_IDX  (OFF_LOSS + 1)
#define OFF_CS   (OFF_IDX + N_TOK)
#define OFF_AVG  (OFF_CS + NCODE)
#define OFF_EMB  (OFF_AVG + NCODE * DIM)

#define TILE_B   10240                   // 128 rows x 80 B (64 B data + pad)

__device__ __align__(16) float g_enorm[NCODE];
__device__ float g_counts[NCODE];
__device__ __align__(16) float g_esum[NCODE * DIM];
__device__ float g_loss;
__device__ float g_nsum;
// tile-contiguous bf16 images: gAt[block][kc][row*80 + c*2], gBt[n][kc][...]
__device__ __align__(16) uint8_t gAt[(N_TOK / 128) * 8 * TILE_B];   // 21 MB
__device__ __align__(16) uint8_t gBt[(NCODE / 128) * 8 * TILE_B];   // 655 KB
__device__ int g_cnt[N_TOK];
__device__ unsigned g_minu[N_TOK];
__device__ unsigned long long g_cand64[N_TOK * CAP];   // (mapped dist, code)

// ---------------------------------------------------------------------------
__device__ __forceinline__ uint32_t smem_u32(const void* p) {
    uint32_t a;
    asm("{ .reg .u64 t; cvta.to.shared.u64 t, %1; cvt.u32.u64 %0, t; }"
        : "=r"(a) : "l"(p));
    return a;
}
#define MBAR_INIT(a, c) asm volatile("mbarrier.init.shared.b64 [%0], %1;" \
    :: "r"(a), "r"(c) : "memory")
#define MBAR_EXPECT_TX(a, b) asm volatile(                                    \
    "mbarrier.arrive.expect_tx.shared.b64 _, [%0], %1;"                       \
    :: "r"(a), "r"(b) : "memory")
#define MBAR_WAIT(a, ph) do {                                               \
    uint32_t _m = (a), _p = (ph), _d;                                       \
    asm volatile("{\n\t.reg .pred p;\n\t"                                   \
        "mbarrier.try_wait.parity.acquire.cta.shared::cta.b64 p, [%1], %2;\n\t" \
        "selp.b32 %0, 1, 0, p;\n\t}" : "=r"(_d) : "r"(_m), "r"(_p) : "memory"); \
    if (!_d) {                                                              \
        asm volatile("{\n\t.reg .pred P1;\n\tWL%=:\n\t"                     \
            "mbarrier.try_wait.parity.acquire.cta.shared::cta.b64 P1, [%0], %1, 0x989680;\n\t" \
            "@P1 bra.uni WD%=;\n\tbra.uni WL%=;\n\tWD%=:\n\t}"              \
            :: "r"(_m), "r"(_p) : "memory");                                \
    } } while (0)
#define FENCE_ASYNC() asm volatile("fence.proxy.async.shared::cta;" ::: "memory")

__device__ __forceinline__ void bulk_g2s(uint32_t dst, const void* src,
                                         uint32_t bytes, uint32_t mbar) {
    asm volatile(
        "cp.async.bulk.shared::cta.global.mbarrier::complete_tx::bytes "
        "[%0], [%1], %2, [%3];"
        :: "r"(dst), "l"(__cvta_generic_to_global(src)), "r"(bytes), "r"(mbar)
        : "memory");
}
__device__ __forceinline__ void red_add_v4(float* gptr, float4 v) {
    asm volatile("red.global.add.v4.f32 [%0], {%1, %2, %3, %4};"
                 :: "l"(__cvta_generic_to_global(gptr)),
                    "f"(v.x), "f"(v.y), "f"(v.z), "f"(v.w) : "memory");
}

#define LDSM4(r0, r1, r2, r3, addr) asm volatile(                              \
    "ldmatrix.sync.aligned.m8n8.x4.shared.b16 {%0,%1,%2,%3}, [%4];"            \
    : "=r"(r0), "=r"(r1), "=r"(r2), "=r"(r3) : "r"(addr))

#define MMA(c, a0, a1, a2, a3, b0, b1) asm volatile(                           \
    "mma.sync.aligned.m16n8k16.row.col.f32.bf16.bf16.f32 "                     \
    "{%0,%1,%2,%3},{%4,%5,%6,%7},{%8,%9},{%0,%1,%2,%3};"                       \
    : "+f"((c)[0]), "+f"((c)[1]), "+f"((c)[2]), "+f"((c)[3])                   \
    : "r"(a0), "r"(a1), "r"(a2), "r"(a3), "r"(b0), "r"(b1))

__device__ __forceinline__ unsigned mapf(float d) {
    unsigned u = __float_as_uint(d);
    return (u & 0x80000000u) ? ~u : (u | 0x80000000u);
}
__device__ __forceinline__ float unmapf(unsigned x) {
    return (x & 0x80000000u) ? __uint_as_float(x & 0x7fffffffu)
                             : __uint_as_float(~x);
}

// ---------------------------------------------------------------------------
__global__ void enorm_kernel(const float* __restrict__ emb) {
    int w = (blockIdx.x * blockDim.x + threadIdx.x) >> 5;
    int lane = threadIdx.x & 31;
    if (w >= NCODE) return;
    const float4* p = (const float4*)(emb + (size_t)w * DIM);
    float s = 0.0f;
#pragma unroll
    for (int c = 0; c < 2; c++) {
        float4 v = p[lane + 32 * c];
        s += v.x * v.x + v.y * v.y + v.z * v.z + v.w * v.w;
    }
#pragma unroll
    for (int o = 16; o >= 1; o >>= 1) s += __shfl_xor_sync(0xffffffffu, s, o);
    if (lane == 0) g_enorm[w] = s;
}

// prep: fp32 -> bf16 into tile-contiguous layout; also zeroes scratch.
#define AC (N_TOK * DIM / 8)             // 1,048,576
#define BC (NCODE * DIM / 8)             // 32,768
#define ZC (NCODE * DIM / 4)             // 65,536
__global__ void prep_kernel(const float* __restrict__ z, const float* __restrict__ emb) {
    int p = blockIdx.x * blockDim.x + threadIdx.x;
    if (p < AC) {
        int t = p >> 9, w = p & 511;             // tile, chunk-within
        int row = w >> 2, c4 = w & 3;
        int b = t >> 3, kc = t & 7;
        const float* src = z + (size_t)(b * 128 + row) * DIM + kc * 32 + c4 * 8;
        float4 v0 = *(const float4*)src;
        float4 v1 = *(const float4*)(src + 4);
        __nv_bfloat162 o0 = __halves2bfloat162(__float2bfloat16_rn(v0.x), __float2bfloat16_rn(v0.y));
        __nv_bfloat162 o1 = __halves2bfloat162(__float2bfloat16_rn(v0.z), __float2bfloat16_rn(v0.w));
        __nv_bfloat162 o2 = __halves2bfloat162(__float2bfloat16_rn(v1.x), __float2bfloat16_rn(v1.y));
        __nv_bfloat162 o3 = __halves2bfloat162(__float2bfloat16_rn(v1.z), __float2bfloat16_rn(v1.w));
        uint4 pack = {*(uint32_t*)&o0, *(uint32_t*)&o1, *(uint32_t*)&o2, *(uint32_t*)&o3};
        *(uint4*)(gAt + (size_t)t * TILE_B + row * 80 + c4 * 16) = pack;
    } else if (p < AC + BC) {
        int q = p - AC;
        int t = q >> 9, w = q & 511;
        int row = w >> 2, c4 = w & 3;
        int n = t >> 3, kc = t & 7;
        const float* src = emb + (size_t)(n * 128 + row) * DIM + kc * 32 + c4 * 8;
        float4 v0 = *(const float4*)src;
        float4 v1 = *(const float4*)(src + 4);
        __nv_bfloat162 o0 = __halves2bfloat162(__float2bfloat16_rn(v0.x), __float2bfloat16_rn(v0.y));
        __nv_bfloat162 o1 = __halves2bfloat162(__float2bfloat16_rn(v0.z), __float2bfloat16_rn(v0.w));
        __nv_bfloat162 o2 = __halves2bfloat162(__float2bfloat16_rn(v1.x), __float2bfloat16_rn(v1.y));
        __nv_bfloat162 o3 = __halves2bfloat162(__float2bfloat16_rn(v1.z), __float2bfloat16_rn(v1.w));
        uint4 pack = {*(uint32_t*)&o0, *(uint32_t*)&o1, *(uint32_t*)&o2, *(uint32_t*)&o3};
        *(uint4*)(gBt + (size_t)t * TILE_B + row * 80 + c4 * 16) = pack;
    } else {
        int zi = p - AC - BC;
        if (zi >= ZC) return;
        ((float4*)g_esum)[zi] = make_float4(0.f, 0.f, 0.f, 0.f);
        if (zi < NCODE / 4) ((float4*)g_counts)[zi] = make_float4(0.f, 0.f, 0.f, 0.f);
        if (zi == 0) g_loss = 0.0f;
    }
}

// ---------------------------------------------------------------------------
// Main: bulk-copy-fed bf16 HMMA approx GEMM + windowed candidate collection.
// ---------------------------------------------------------------------------
#define STAGE_SZ 20480                   // A 10240 + B 10240
#define SM_EN    81920                   // 4 KB
#define SM_MINU  86016                   // 128 x u32
#define SM_CNT   86528                   // 128 x int
#define SM_MBAR  87040                   // 4 x 8 B
#define SM_TOTAL 87104

__global__ __launch_bounds__(256, 2)
void vq_main_kernel() {
    extern __shared__ char smem[];
    const uint32_t sb = smem_u32(smem);
    const int tid  = threadIdx.x;
    const int lane = tid & 31;
    const int wid  = tid >> 5;
    const int wm   = wid >> 2;           // 0..1  (M half)
    const int wn   = wid & 3;            // 0..3  (N quarter, 32 cols)
    const int rowBase = blockIdx.x * 128;

    float*    sEnorm = (float*)(smem + SM_EN);
    unsigned* sMinU  = (unsigned*)(smem + SM_MINU);
    int*      sCnt   = (int*)(smem + SM_CNT);

#pragma unroll
    for (int i = 0; i < 4; i++) sEnorm[tid + i * 256] = g_enorm[tid + i * 256];
    if (tid < 128) { sMinU[tid] = 0xffffffffu; sCnt[tid] = 0; }
    if (tid == 0) {
#pragma unroll
        for (int s = 0; s < 4; s++) MBAR_INIT(sb + SM_MBAR + s * 8, 1);
    }
    __syncthreads();
    FENCE_ASYNC();

    // producer: j = n*8 + kc
#define ISSUE(j) do {                                                          \
    int _s = (j) & 3;                                                          \
    uint32_t _st = sb + _s * STAGE_SZ;                                         \
    uint32_t _mb = sb + SM_MBAR + _s * 8;                                      \
    MBAR_EXPECT_TX(_mb, STAGE_SZ);                                             \
    bulk_g2s(_st, gAt + (size_t)(blockIdx.x * 8 + ((j) & 7)) * TILE_B,         \
             TILE_B, _mb);                                                     \
    bulk_g2s(_st + TILE_B, gBt + (size_t)(j) * TILE_B, TILE_B, _mb);           \
} while (0)

    if (tid == 0) { ISSUE(0); ISSUE(1); ISSUE(2); }

    // ldmatrix per-lane address offsets (bytes), row stride 80B
    const uint32_t aOff = (uint32_t)((wm * 64 + (lane & 15)) * 80 + (lane >> 4) * 16);
    const uint32_t bOff = (uint32_t)((wn * 32 + (lane & 7) + ((lane >> 4) << 3)) * 80
                                     + ((lane >> 3) & 1) * 16);

    float acc[4][4][4];
#pragma unroll
    for (int m = 0; m < 4; m++)
#pragma unroll
        for (int nf = 0; nf < 4; nf++)
#pragma unroll
            for (int v = 0; v < 4; v++) acc[m][nf][v] = 0.0f;

    // smem counter, direct global store of packed (dist, code)
#define EMIT(dd, cc, rloc) do {                                                \
    int _p = atomicAdd(&sCnt[rloc], 1);                                        \
    if (_p < CAP)                                                              \
        g_cand64[(size_t)(rowBase + (rloc)) * CAP + _p] =                      \
            ((unsigned long long)mapf(dd) << 32) | (unsigned)(cc);             \
} while (0)

    for (int it = 0; it < 64; it++) {
        MBAR_WAIT(sb + SM_MBAR + (it & 3) * 8, (it >> 2) & 1);
        // stage (it+3)&3 == (it-1)&3 was fully consumed before the barrier at
        // the end of iteration it-1, so re-arm it now for max overlap.
        if (tid == 0 && it + 3 < 64) ISSUE(it + 3);

        const uint32_t stBase = sb + (it & 3) * STAGE_SZ;
        const uint32_t aB = stBase + aOff;
        const uint32_t bB = stBase + TILE_B + bOff;

#pragma unroll
        for (int s = 0; s < 2; s++) {                    // two k16 steps
            uint32_t b[4][2];
#pragma unroll
            for (int q = 0; q < 2; q++) {
                uint32_t r0, r1, r2, r3;
                LDSM4(r0, r1, r2, r3, bB + q * 1280 + s * 32);
                b[2 * q][0] = r0; b[2 * q][1] = r1;
                b[2 * q + 1][0] = r2; b[2 * q + 1][1] = r3;
            }
#pragma unroll
            for (int m = 0; m < 4; m++) {
                uint32_t a0, a1, a2, a3;
                LDSM4(a0, a1, a2, a3, aB + m * 1280 + s * 32);
#pragma unroll
                for (int nf = 0; nf < 4; nf++)
                    MMA(acc[m][nf], a0, a1, a2, a3, b[nf][0], b[nf][1]);
            }
        }

        if ((it & 7) == 7) {                             // end of n-tile
            const int n = it >> 3;
            const int colB = n * 128 + wn * 32 + 2 * (lane & 3);
            // pass 1: settle per-row approx min
#pragma unroll
            for (int m = 0; m < 4; m++) {
                int r0 = wm * 64 + m * 16 + (lane >> 2);
                float bd0 = 3.4e38f, bd1 = 3.4e38f;
#pragma unroll
                for (int nf = 0; nf < 4; nf++) {
                    float2 en = *(const float2*)&sEnorm[colB + nf * 8];
                    bd0 = fminf(bd0, fminf(en.x - 2.0f * acc[m][nf][0],
                                           en.y - 2.0f * acc[m][nf][1]));
                    bd1 = fminf(bd1, fminf(en.x - 2.0f * acc[m][nf][2],
                                           en.y - 2.0f * acc[m][nf][3]));
                }
#pragma unroll
                for (int off = 1; off <= 2; off <<= 1) {
                    bd0 = fminf(bd0, __shfl_xor_sync(0xffffffffu, bd0, off));
                    bd1 = fminf(bd1, __shfl_xor_sync(0xffffffffu, bd1, off));
                }
                if ((lane & 3) == 0) {
                    atomicMin(&sMinU[r0], mapf(bd0));
                    atomicMin(&sMinU[r0 + 8], mapf(bd1));
                }
            }
            __syncthreads();
            // pass 2: emit candidates within TAU of settled min
#pragma unroll
            for (int m = 0; m < 4; m++) {
                int r0 = wm * 64 + m * 16 + (lane >> 2);
                float thr0 = unmapf(sMinU[r0]) + TAU;
                float thr1 = unmapf(sMinU[r0 + 8]) + TAU;
#pragma unroll
                for (int nf = 0; nf < 4; nf++) {
                    float2 en = *(const float2*)&sEnorm[colB + nf * 8];
                    float d0 = en.x - 2.0f * acc[m][nf][0];
                    float d1 = en.y - 2.0f * acc[m][nf][1];
                    float d2 = en.x - 2.0f * acc[m][nf][2];
                    float d3 = en.y - 2.0f * acc[m][nf][3];
                    int c0 = colB + nf * 8;
                    if (d0 < thr0) EMIT(d0, c0,     r0);
                    if (d1 < thr0) EMIT(d1, c0 + 1, r0);
                    if (d2 < thr1) EMIT(d2, c0,     r0 + 8);
                    if (d3 < thr1) EMIT(d3, c0 + 1, r0 + 8);
                    acc[m][nf][0] = 0.0f; acc[m][nf][1] = 0.0f;
                    acc[m][nf][2] = 0.0f; acc[m][nf][3] = 0.0f;
                }
            }
        }
        __syncthreads();                                 // stage consumed
    }

    // dump counts (clamped) + final per-row approx min
    if (tid < 128) {
        int c = sCnt[tid];
        g_cnt[rowBase + tid]  = c > CAP ? CAP : c;
        g_minu[rowBase + tid] = sMinU[tid];
    }
}

// ---------------------------------------------------------------------------
// Refine + output kernel: grid N_TOK/16, 256 threads.
// Phase A: lane-parallel candidate scan (one coalesced load + ballot of the
//          TAU2 survivors), then warp-cooperative exact fp32 refinement of
//          only the surviving candidates (typically 1-2 per row).
// Phase B: vectorized float4 z_q_st / loss / esum.
// ---------------------------------------------------------------------------
__global__ __launch_bounds__(256, 8)
void outref_kernel(const float* __restrict__ z, const float* __restrict__ emb,
                   float* __restrict__ out) {
    __shared__ int   sBestC[16];
    __shared__ float sRed[8];
    const int tid  = threadIdx.x;
    const int lane = tid & 31;
    const int wid  = tid >> 5;
    const int rowBase = blockIdx.x * 16;

#pragma unroll
    for (int rr = 0; rr < 2; rr++) {
        int r = rowBase + wid * 2 + rr;
        int cnt = g_cnt[r];
        unsigned mthr = mapf(unmapf(g_minu[r]) + TAU2);
        const float* zr = z + (size_t)r * DIM;
        float zv[8];
#pragma unroll
        for (int j = 0; j < 8; j++) zv[j] = zr[lane + 32 * j];
        float bestd = 3.4e38f; int bestc = 0x7fffffff;
        for (int base = 0; base < cnt; base += 32) {     // almost always 1 pass
            int ci = base + lane;
            unsigned long long pk = ~0ull;
            if (ci < cnt) pk = g_cand64[(size_t)r * CAP + ci];  // coalesced
            bool pass = (ci < cnt) && ((unsigned)(pk >> 32) <= mthr);
            unsigned msk = __ballot_sync(0xffffffffu, pass);
            while (msk) {                                // survivors: ~1-2
                int src = __ffs(msk) - 1; msk &= msk - 1;
                unsigned long long cpk = __shfl_sync(0xffffffffu, pk, src);
                int c = (int)(unsigned)(cpk & 0xffffffffull);
                const float* er = emb + (size_t)c * DIM;
                float dot = 0.0f;
#pragma unroll
                for (int j = 0; j < 8; j++) dot += zv[j] * er[lane + 32 * j];
#pragma unroll
                for (int o = 16; o >= 1; o >>= 1)
                    dot += __shfl_xor_sync(0xffffffffu, dot, o);
                float dd = g_enorm[c] - 2.0f * dot;
                if (dd < bestd || (dd == bestd && c < bestc)) { bestd = dd; bestc = c; }
            }
        }
        if (lane == 0) {
            sBestC[wid * 2 + rr] = bestc;
            out[OFF_IDX + r] = (float)bestc;
            atomicAdd(&g_counts[bestc], 1.0f);
        }
    }
    __syncthreads();

    // phase B: 4 row-groups x 64 column-threads, float4 everywhere
    float lossAcc = 0.0f;
    const int c4 = (tid & 63) * 4;
    const int rg = tid >> 6;
#pragma unroll
    for (int k = 0; k < 4; k++) {
        int rr   = rg * 4 + k;
        int code = sBestC[rr];
        int row  = rowBase + rr;
        float4 e  = *(const float4*)(emb + (size_t)code * DIM + c4);
        float4 zv = *(const float4*)(z + (size_t)row * DIM + c4);
        float4 df = make_float4(e.x - zv.x, e.y - zv.y, e.z - zv.z, e.w - zv.w);
        float4 q  = make_float4(zv.x + df.x, zv.y + df.y, zv.z + df.z, zv.w + df.w);
        *(float4*)(out + OFF_ZQ + (size_t)row * DIM + c4) = q;
        lossAcc += df.x * df.x + df.y * df.y + df.z * df.z + df.w * df.w;
        red_add_v4(&g_esum[code * DIM + c4], zv);
    }
#pragma unroll
    for (int o = 16; o >= 1; o >>= 1) lossAcc += __shfl_xor_sync(0xffffffffu, lossAcc, o);
    if (lane == 0) sRed[wid] = lossAcc;
    __syncthreads();
    if (tid < 8) {
        float v = sRed[tid];
#pragma unroll
        for (int o = 4; o >= 1; o >>= 1) v += __shfl_xor_sync(0xffu, v, o, 8);
        if (tid == 0) atomicAdd(&g_loss, v);
    }
}

// ---------------------------------------------------------------------------
__global__ void fin1_kernel(const float* __restrict__ cs, float* __restrict__ out) {
    int k = threadIdx.x;
    float ncs = cs[k] * 0.99f + 0.01f * g_counts[k];
    out[OFF_CS + k] = ncs;
    __shared__ float red[32];
    float v = ncs;
#pragma unroll
    for (int o = 16; o >= 1; o >>= 1) v += __shfl_xor_sync(0xffffffffu, v, o);
    if ((k & 31) == 0) red[k >> 5] = v;
    __syncthreads();
    if (k < 32) {
        float t = red[k];
#pragma unroll
        for (int o = 16; o >= 1; o >>= 1) t += __shfl_xor_sync(0xffffffffu, t, o);
        if (k == 0) {
            g_nsum = t;
            out[OFF_LOSS] = 0.25f * g_loss / (float)(N_TOK * DIM);
        }
    }
}

__global__ void fin2_kernel(const float* __restrict__ avg, float* __restrict__ out) {
    int i = blockIdx.x * blockDim.x + threadIdx.x;
    float navg = avg[i] * 0.99f + 0.01f * g_esum[i];
    out[OFF_AVG + i] = navg;
    int k = i >> 8;
    float ncs = out[OFF_CS + k];
    float csn = (ncs + 1e-6f) / (g_nsum + (float)NCODE * 1e-6f);
    out[OFF_EMB + i] = navg / csn;
}

// ---------------------------------------------------------------------------
extern "C" void kernel_launch(void* const* d_in, const int* in_sizes, int n_in,
                              void* d_out, int out_size) {
    const float* z   = (const float*)d_in[0];
    const float* emb = (const float*)d_in[1];
    const float* cs  = (const float*)d_in[2];
    const float* avg = (const float*)d_in[3];
    float* out = (float*)d_out;

    cudaFuncSetAttribute(vq_main_kernel,
                         cudaFuncAttributeMaxDynamicSharedMemorySize, SM_TOTAL);

    enorm_kernel<<<(NCODE * 32) / 256, 256>>>(emb);
    prep_kernel<<<(AC + BC + ZC + 255) / 256, 256>>>(z, emb);
    vq_main_kernel<<<N_TOK / 128, 256, SM_TOTAL>>>();
    outref_kernel<<<N_TOK / 16, 256>>>(z, emb, out);
    fin1_kernel<<<1, 1024>>>(cs, out);
    fin2_kernel<<<(NCODE * DIM) / 256, 256>>>(avg, out);
}